// round 6
// baseline (speedup 1.0000x reference)
#include <cuda_runtime.h>
#include <cstdint>

// Problem constants (B=2, T=2048, C=1024, H=16, hd=64, MLP width 32)
#define BSZ   2
#define TSEQ  2048
#define CDIM  1024
#define NH    16
#define HD    64
#define MLPW  32

__device__ float g_qkv[3 * BSZ * NH * TSEQ * HD];
__device__ float g_y[BSZ * TSEQ * CDIM];
__device__ float g_utab[TSEQ];   // log(|c*rel|+1)
__device__ float g_invP[TSEQ];   // 1/(log(|c*max(t,thr)|+1)+eps)

// ===========================================================================
// Helpers
// ===========================================================================
__device__ __forceinline__ uint32_t smem_u32(const void* p) {
    uint32_t a;
    asm("{ .reg .u64 t; cvta.to.shared.u64 t, %1; cvt.u32.u64 %0, t; }"
        : "=r"(a) : "l"(p));
    return a;
}
__device__ __forceinline__ uint32_t f2tf32(float f) {
    uint32_t r;
    asm("cvt.rna.tf32.f32 %0, %1;" : "=r"(r) : "f"(f));
    return r;
}
__device__ __forceinline__ float rnaf(float f) {
    return __uint_as_float(f2tf32(f));
}
__device__ __forceinline__ void mma8(float* c, const uint32_t* a,
                                     const uint32_t* b) {
    asm volatile(
        "mma.sync.aligned.m16n8k8.row.col.f32.tf32.tf32.f32 "
        "{%0,%1,%2,%3}, {%4,%5,%6,%7}, {%8,%9}, {%0,%1,%2,%3};"
        : "+f"(c[0]), "+f"(c[1]), "+f"(c[2]), "+f"(c[3])
        : "r"(a[0]), "r"(a[1]), "r"(a[2]), "r"(a[3]), "r"(b[0]), "r"(b[1]));
}
__device__ __forceinline__ void ldm_x4(uint32_t& r0, uint32_t& r1,
                                       uint32_t& r2, uint32_t& r3,
                                       uint32_t addr) {
    asm volatile(
        "ldmatrix.sync.aligned.m8n8.x4.shared.b16 {%0,%1,%2,%3}, [%4];"
        : "=r"(r0), "=r"(r1), "=r"(r2), "=r"(r3) : "r"(addr));
}

// ===========================================================================
// Init: FIRE log tables
// ===========================================================================
__global__ void init_tables(const float* __restrict__ cp,
                            const float* __restrict__ lm) {
    const int i = blockIdx.x * blockDim.x + threadIdx.x;
    if (i >= TSEQ) return;
    const float c   = cp[0];
    const float thr = fabsf(lm[0] * 512.0f);
    g_utab[i] = logf(fabsf(c * (float)i) + 1.0f);
    g_invP[i] = 1.0f / (logf(fabsf(c * fmaxf((float)i, thr)) + 1.0f) + 1e-6f);
}

// ===========================================================================
// tf32 mma.sync GEMM v2: smem holds PRE-CONVERTED tf32 bits.
// 128x128 CTA tile, BK=16, 256 thr / 8 warps (2M x 4N), warp tile 64x32.
// A frags via ldmatrix (pitch 20, conflict-free); B frags scalar LDS
// (pitch 136, conflict-free). LDG->cvt->STS staging, reg-prefetch dbuf.
// ===========================================================================
template <int MODE>
__global__ __launch_bounds__(256, 2) void mma_gemm(const float* __restrict__ A,
                                                   const float* __restrict__ Bm,
                                                   const float* __restrict__ bias,
                                                   float* __restrict__ out,
                                                   int K, int N) {
    __shared__ float As[2][128][20];   // [m][k] tf32-rounded
    __shared__ float Bs[2][16][136];   // [k][n] tf32-rounded

    const int tid   = threadIdx.x;
    const int lane  = tid & 31;
    const int wid   = tid >> 5;
    const int warpM = wid & 1;         // 2 warps over M (64 rows each)
    const int warpN = wid >> 1;        // 4 warps over N (32 cols each)
    const int m0    = blockIdx.y * 128;
    const int n0    = blockIdx.x * 128;

    // A loader: row tid>>1 (0..127), k-offset (tid&1)*8; 2x float4
    const int arow = tid >> 1;
    const int ak   = (tid & 1) * 8;
    const float* Ag = A + (size_t)(m0 + arow) * K + ak;
    // B loader: k-row tid>>4 (0..15), n-offset (tid&15)*8; 2x float4
    const int brow = tid >> 4;
    const int bc   = (tid & 15) * 8;
    const float* Bg = Bm + (size_t)brow * N + n0 + bc;

    float4 ra0, ra1, rb0, rb1;
    ra0 = *(const float4*)Ag;
    ra1 = *(const float4*)(Ag + 4);
    rb0 = *(const float4*)Bg;
    rb1 = *(const float4*)(Bg + 4);

#define STAGE(bi)                                                             \
    do {                                                                      \
        *(float4*)&As[bi][arow][ak] =                                         \
            make_float4(rnaf(ra0.x), rnaf(ra0.y), rnaf(ra0.z), rnaf(ra0.w));  \
        *(float4*)&As[bi][arow][ak + 4] =                                     \
            make_float4(rnaf(ra1.x), rnaf(ra1.y), rnaf(ra1.z), rnaf(ra1.w));  \
        *(float4*)&Bs[bi][brow][bc] =                                         \
            make_float4(rnaf(rb0.x), rnaf(rb0.y), rnaf(rb0.z), rnaf(rb0.w));  \
        *(float4*)&Bs[bi][brow][bc + 4] =                                     \
            make_float4(rnaf(rb1.x), rnaf(rb1.y), rnaf(rb1.z), rnaf(rb1.w));  \
    } while (0)

    STAGE(0);
    __syncthreads();

    float acc[2][4][2][4];  // [mf-pair split below] -> use [4][4][4] flat
    // acc[mf][nf][i], mf=0..3 (16-row frags), nf=0..3 (8-col frags)
    float a4[4][4][4];
#pragma unroll
    for (int mf = 0; mf < 4; mf++)
#pragma unroll
        for (int nf = 0; nf < 4; nf++)
#pragma unroll
            for (int i = 0; i < 4; i++) a4[mf][nf][i] = 0.0f;
    (void)acc;

    const int nk = K >> 4;
#pragma unroll 1
    for (int kt = 0; kt < nk; kt++) {
        const int  buf = kt & 1;
        const bool nxt = (kt + 1) < nk;
        if (nxt) {
            const float* ap = Ag + (kt + 1) * 16;
            ra0 = *(const float4*)ap;
            ra1 = *(const float4*)(ap + 4);
            const float* bp = Bg + (size_t)(kt + 1) * 16 * N;
            rb0 = *(const float4*)bp;
            rb1 = *(const float4*)(bp + 4);
        }

        const uint32_t abase = smem_u32(&As[buf][0][0]);
#pragma unroll
        for (int ks = 0; ks < 2; ks++) {
            const int kb = ks * 8;
            uint32_t af[4][4];
#pragma unroll
            for (int mf = 0; mf < 4; mf++) {
                const uint32_t addr = abase +
                    4u * ((uint32_t)(warpM * 64 + mf * 16 + (lane & 15)) * 20u +
                          (uint32_t)kb + ((uint32_t)lane >> 4) * 4u);
                ldm_x4(af[mf][0], af[mf][1], af[mf][2], af[mf][3], addr);
            }
#pragma unroll
            for (int nf = 0; nf < 4; nf++) {
                const int ncol = warpN * 32 + nf * 8 + (lane >> 2);
                uint32_t bfr[2];
                bfr[0] = __float_as_uint(Bs[buf][kb + (lane & 3)][ncol]);
                bfr[1] = __float_as_uint(Bs[buf][kb + (lane & 3) + 4][ncol]);
#pragma unroll
                for (int mf = 0; mf < 4; mf++) mma8(a4[mf][nf], af[mf], bfr);
            }
        }

        if (nxt) STAGE(buf ^ 1);
        __syncthreads();
    }
#undef STAGE

    const int r  = lane >> 2;
    const int cq = lane & 3;
#pragma unroll
    for (int mf = 0; mf < 4; mf++) {
#pragma unroll
        for (int nf = 0; nf < 4; nf++) {
            const int n = n0 + warpN * 32 + nf * 8 + 2 * cq;
            const float bx = bias[n], by = bias[n + 1];
#pragma unroll
            for (int half = 0; half < 2; half++) {
                const int m = m0 + warpM * 64 + mf * 16 + r + half * 8;
                float2 v = make_float2(a4[mf][nf][half * 2] + bx,
                                       a4[mf][nf][half * 2 + 1] + by);
                if (MODE == 0) {
                    const int which = n >> 10;
                    const int hh    = (n & 1023) >> 6;
                    const int d     = n & 63;
                    const int bb    = m >> 11;
                    const int t     = m & 2047;
                    *(float2*)&g_qkv[which * (BSZ * NH * TSEQ * HD) +
                                     ((bb * NH + hh) * TSEQ + t) * HD + d] = v;
                } else {
                    *(float2*)&out[(size_t)m * N + n] = v;
                }
            }
        }
    }
}

// ===========================================================================
// FA2-style flash attention, tf32 mma.sync, fused FIRE bias (unchanged R5).
// ===========================================================================
__device__ __forceinline__ float fire_mlp(float nd, const float* sw1,
                                          const float* sb1, const float* sw2,
                                          float b2h) {
    float acc = b2h;
#pragma unroll
    for (int w = 0; w < MLPW; w++)
        acc = fmaf(fmaxf(fmaf(nd, sw1[w], sb1[w]), 0.0f), sw2[w], acc);
    return acc;
}

__global__ __launch_bounds__(256) void attn_mma(
        const float* __restrict__ w1, const float* __restrict__ b1,
        const float* __restrict__ w2, const float* __restrict__ b2) {
    __shared__ __align__(16) float Ks[2][32][68];
    __shared__ __align__(16) float Vt[2][64][36];
    __shared__ float sw1[MLPW], sb1[MLPW], sw2[MLPW];
    __shared__ float s_alpha;
    __shared__ int   s_lin;

    const int tid  = threadIdx.x;
    const int lane = tid & 31;
    const int warp = tid >> 5;
    const int h    = blockIdx.y;
    const int b    = blockIdx.z;
    const int q0   = (gridDim.x - 1 - blockIdx.x) * 128;
    const int tw   = q0 + warp * 16;
    const int r    = lane >> 2;
    const int cq   = lane & 3;
    const int t0   = tw + r;
    const int t1   = t0 + 8;

    if (tid < MLPW) {
        sw1[tid] = w1[tid];
        sb1[tid] = b1[tid];
        sw2[tid] = w2[tid * NH + h];
    }
    __syncthreads();
    if (tid == 0) {
        bool  lin = true;
        float a   = 0.0f;
#pragma unroll
        for (int w = 0; w < MLPW; w++) {
            lin = lin && (sb1[w] == 0.0f);
            a   = fmaf(fmaxf(sw1[w], 0.0f), sw2[w], a);
        }
        s_alpha = a;
        s_lin   = lin ? 1 : 0;
    }

    const float b2h   = b2[h];
    const float invP0 = g_invP[t0];
    const float invP1 = g_invP[t1];

    const float* Qg = g_qkv + (size_t)(b * NH + h) * TSEQ * HD;
    const float* Kg = Qg + (size_t)BSZ * NH * TSEQ * HD;
    const float* Vg = Kg + (size_t)BSZ * NH * TSEQ * HD;

    uint32_t qa[8][4];
#pragma unroll
    for (int kf = 0; kf < 8; kf++) {
        qa[kf][0] = f2tf32(Qg[(size_t)t0 * HD + kf * 8 + cq] * 0.125f);
        qa[kf][1] = f2tf32(Qg[(size_t)t1 * HD + kf * 8 + cq] * 0.125f);
        qa[kf][2] = f2tf32(Qg[(size_t)t0 * HD + kf * 8 + cq + 4] * 0.125f);
        qa[kf][3] = f2tf32(Qg[(size_t)t1 * HD + kf * 8 + cq + 4] * 0.125f);
    }

    float o[8][4];
#pragma unroll
    for (int nd = 0; nd < 8; nd++)
#pragma unroll
        for (int i = 0; i < 4; i++) o[nd][i] = 0.0f;
    float m0 = -1e30f, m1 = -1e30f, l0 = 0.0f, l1 = 0.0f;

    const int krow = tid >> 3;
    const int kc   = tid & 7;
    float4 kreg0, kreg1;
    float  vreg[8];

    {
        const float4* kp = (const float4*)&Kg[(size_t)krow * HD];
        kreg0 = kp[kc];
        kreg1 = kp[kc + 8];
#pragma unroll
        for (int i = 0; i < 8; i++)
            vreg[i] = Vg[(size_t)krow * HD + kc + 8 * i];
        float4 c0 = make_float4(rnaf(kreg0.x), rnaf(kreg0.y), rnaf(kreg0.z), rnaf(kreg0.w));
        float4 c1 = make_float4(rnaf(kreg1.x), rnaf(kreg1.y), rnaf(kreg1.z), rnaf(kreg1.w));
        *(float4*)&Ks[0][krow][kc * 4]      = c0;
        *(float4*)&Ks[0][krow][kc * 4 + 32] = c1;
#pragma unroll
        for (int i = 0; i < 8; i++) Vt[0][kc + 8 * i][krow] = rnaf(vreg[i]);
    }
    __syncthreads();

    const int   lin   = s_lin;
    const float alpha = s_alpha;
    const float ai0   = alpha * invP0;
    const float ai1   = alpha * invP1;

    const int nt = (q0 + 128) >> 5;
#pragma unroll 1
    for (int it = 0; it < nt; it++) {
        const int  buf = it & 1;
        const int  s0  = it * 32;
        const bool nxt = (it + 1) < nt;

        if (nxt) {
            const float4* kp = (const float4*)&Kg[(size_t)(s0 + 32 + krow) * HD];
            kreg0 = kp[kc];
            kreg1 = kp[kc + 8];
#pragma unroll
            for (int i = 0; i < 8; i++)
                vreg[i] = Vg[(size_t)(s0 + 32 + krow) * HD + kc + 8 * i];
        }

        if (s0 <= tw + 15) {
            const bool     msk = (s0 + 31) > tw;
            const uint32_t kb  = smem_u32(&Ks[buf][0][0]);
            const uint32_t vb  = smem_u32(&Vt[buf][0][0]);

            float s[4][4];
#pragma unroll
            for (int nf = 0; nf < 4; nf++) {
                s[nf][0] = s[nf][1] = s[nf][2] = s[nf][3] = 0.0f;
#pragma unroll
                for (int kfp = 0; kfp < 4; kfp++) {
                    uint32_t bb[4];
                    const uint32_t addr = kb +
                        4u * ((uint32_t)(8 * nf + (lane & 7)) * 68u +
                              16u * kfp + 4u * (lane >> 3));
                    ldm_x4(bb[0], bb[1], bb[2], bb[3], addr);
                    mma8(s[nf], qa[2 * kfp], bb);
                    mma8(s[nf], qa[2 * kfp + 1], bb + 2);
                }
            }

            float mt0 = -1e30f, mt1 = -1e30f;
#pragma unroll
            for (int nf = 0; nf < 4; nf++) {
                const int k0    = s0 + nf * 8 + 2 * cq;
                const int rel00 = t0 - k0;
                const int rel01 = rel00 - 1;
                const int rel10 = rel00 + 8;
                const int rel11 = rel00 + 7;
                const float u00 = __ldg(&g_utab[rel00 < 0 ? 0 : rel00]);
                const float u01 = __ldg(&g_utab[rel01 < 0 ? 0 : rel01]);
                const float u10 = __ldg(&g_utab[rel10 < 0 ? 0 : rel10]);
                const float u11 = __ldg(&g_utab[rel11 < 0 ? 0 : rel11]);
                float b00, b01, b10, b11;
                if (lin) {
                    b00 = fmaf(ai0, u00, b2h);
                    b01 = fmaf(ai0, u01, b2h);
                    b10 = fmaf(ai1, u10, b2h);
                    b11 = fmaf(ai1, u11, b2h);
                } else {
                    b00 = fire_mlp(u00 * invP0, sw1, sb1, sw2, b2h);
                    b01 = fire_mlp(u01 * invP0, sw1, sb1, sw2, b2h);
                    b10 = fire_mlp(u10 * invP1, sw1, sb1, sw2, b2h);
                    b11 = fire_mlp(u11 * invP1, sw1, sb1, sw2, b2h);
                }
                s[nf][0] += b00;
                s[nf][1] += b01;
                s[nf][2] += b10;
                s[nf][3] += b11;
                if (msk) {
                    if (rel00 < 0) s[nf][0] = -1e30f;
                    if (rel01 < 0) s[nf][1] = -1e30f;
                    if (rel10 < 0) s[nf][2] = -1e30f;
                    if (rel11 < 0) s[nf][3] = -1e30f;
                }
                mt0 = fmaxf(mt0, fmaxf(s[nf][0], s[nf][1]));
                mt1 = fmaxf(mt1, fmaxf(s[nf][2], s[nf][3]));
            }
            mt0 = fmaxf(mt0, __shfl_xor_sync(0xffffffffu, mt0, 1));
            mt0 = fmaxf(mt0, __shfl_xor_sync(0xffffffffu, mt0, 2));
            mt1 = fmaxf(mt1, __shfl_xor_sync(0xffffffffu, mt1, 1));
            mt1 = fmaxf(mt1, __shfl_xor_sync(0xffffffffu, mt1, 2));

            const float mn0 = fmaxf(m0, mt0);
            const float mn1 = fmaxf(m1, mt1);
            const float f0  = __expf(m0 - mn0);
            const float f1  = __expf(m1 - mn1);
            m0 = mn0; m1 = mn1;
            l0 *= f0;  l1 *= f1;
#pragma unroll
            for (int nd = 0; nd < 8; nd++) {
                o[nd][0] *= f0; o[nd][1] *= f0;
                o[nd][2] *= f1; o[nd][3] *= f1;
            }
#pragma unroll
            for (int nf = 0; nf < 4; nf++) {
                s[nf][0] = __expf(s[nf][0] - m0);
                s[nf][1] = __expf(s[nf][1] - m0);
                s[nf][2] = __expf(s[nf][2] - m1);
                s[nf][3] = __expf(s[nf][3] - m1);
                l0 += s[nf][0] + s[nf][1];
                l1 += s[nf][2] + s[nf][3];
            }

            const int src1 = (lane & 28) | (cq >> 1);
            const int src2 = src1 + 2;
#pragma unroll
            for (int kf2 = 0; kf2 < 4; kf2++) {
                const float x0 = __shfl_sync(0xffffffffu, s[kf2][0], src1);
                const float x1 = __shfl_sync(0xffffffffu, s[kf2][1], src1);
                const float y0 = __shfl_sync(0xffffffffu, s[kf2][0], src2);
                const float y1 = __shfl_sync(0xffffffffu, s[kf2][1], src2);
                const float x2 = __shfl_sync(0xffffffffu, s[kf2][2], src1);
                const float x3 = __shfl_sync(0xffffffffu, s[kf2][3], src1);
                const float y2 = __shfl_sync(0xffffffffu, s[kf2][2], src2);
                const float y3 = __shfl_sync(0xffffffffu, s[kf2][3], src2);
                uint32_t pa[4];
                pa[0] = f2tf32((cq & 1) ? x1 : x0);
                pa[1] = f2tf32((cq & 1) ? x3 : x2);
                pa[2] = f2tf32((cq & 1) ? y1 : y0);
                pa[3] = f2tf32((cq & 1) ? y3 : y2);
#pragma unroll
                for (int g = 0; g < 4; g++) {
                    uint32_t bv[4];
                    const uint32_t addr = vb +
                        4u * ((uint32_t)(8 * (2 * g + (lane >> 4)) + (lane & 7)) * 36u +
                              8u * kf2 + 4u * ((lane >> 3) & 1));
                    ldm_x4(bv[0], bv[1], bv[2], bv[3], addr);
                    mma8(o[2 * g], pa, bv);
                    mma8(o[2 * g + 1], pa, bv + 2);
                }
            }
        }

        if (nxt) {
            const int nb = buf ^ 1;
            float4 c0 = make_float4(rnaf(kreg0.x), rnaf(kreg0.y), rnaf(kreg0.z), rnaf(kreg0.w));
            float4 c1 = make_float4(rnaf(kreg1.x), rnaf(kreg1.y), rnaf(kreg1.z), rnaf(kreg1.w));
            *(float4*)&Ks[nb][krow][kc * 4]      = c0;
            *(float4*)&Ks[nb][krow][kc * 4 + 32] = c1;
#pragma unroll
            for (int i = 0; i < 8; i++) Vt[nb][kc + 8 * i][krow] = rnaf(vreg[i]);
        }
        __syncthreads();
    }

    l0 += __shfl_xor_sync(0xffffffffu, l0, 1);
    l0 += __shfl_xor_sync(0xffffffffu, l0, 2);
    l1 += __shfl_xor_sync(0xffffffffu, l1, 1);
    l1 += __shfl_xor_sync(0xffffffffu, l1, 2);
    const float inv0 = 1.0f / l0;
    const float inv1 = 1.0f / l1;
    float* y0p = &g_y[((size_t)(b * TSEQ) + t0) * CDIM + h * HD];
    float* y1p = &g_y[((size_t)(b * TSEQ) + t1) * CDIM + h * HD];
#pragma unroll
    for (int nd = 0; nd < 8; nd++) {
        const int d = nd * 8 + 2 * cq;
        *(float2*)&y0p[d] = make_float2(o[nd][0] * inv0, o[nd][1] * inv0);
        *(float2*)&y1p[d] = make_float2(o[nd][2] * inv1, o[nd][3] * inv1);
    }
}

// ===========================================================================
// Launch
// ===========================================================================
extern "C" void kernel_launch(void* const* d_in, const int* in_sizes, int n_in,
                              void* d_out, int out_size) {
    const float* x     = (const float*)d_in[0];
    const float* Wqkv  = (const float*)d_in[1];
    const float* bqkv  = (const float*)d_in[2];
    const float* Wproj = (const float*)d_in[3];
    const float* bproj = (const float*)d_in[4];
    const float* w1    = (const float*)d_in[5];
    const float* b1    = (const float*)d_in[6];
    const float* w2    = (const float*)d_in[7];
    const float* b2    = (const float*)d_in[8];
    const float* cpar  = (const float*)d_in[9];
    const float* lmul  = (const float*)d_in[10];
    float* out = (float*)d_out;

    init_tables<<<TSEQ / 256, 256>>>(cpar, lmul);

    mma_gemm<0><<<dim3(3 * CDIM / 128, BSZ * TSEQ / 128), 256>>>(
        x, Wqkv, bqkv, nullptr, CDIM, 3 * CDIM);

    attn_mma<<<dim3(TSEQ / 128, NH, BSZ), 256>>>(w1, b1, w2, b2);

    float* gy_ptr = nullptr;
    cudaGetSymbolAddress((void**)&gy_ptr, g_y);
    mma_gemm<1><<<dim3(CDIM / 128, BSZ * TSEQ / 128), 256>>>(
        gy_ptr, Wproj, bproj, out, CDIM, CDIM);
}

// round 7
// speedup vs baseline: 1.1061x; 1.1061x over previous
#include <cuda_runtime.h>
#include <cstdint>

// Problem constants (B=2, T=2048, C=1024, H=16, hd=64, MLP width 32)
#define BSZ   2
#define TSEQ  2048
#define CDIM  1024
#define NH    16
#define HD    64
#define MLPW  32
#define UPAD  64

__device__ float g_qkv[3 * BSZ * NH * TSEQ * HD];
__device__ float g_y[BSZ * TSEQ * CDIM];
__device__ float g_ut2[TSEQ + UPAD];  // log(|c*max(i-UPAD,0)|+1)
__device__ float g_invP[TSEQ];        // 1/(log(|c*max(t,thr)|+1)+eps)

// ===========================================================================
// Helpers
// ===========================================================================
__device__ __forceinline__ uint32_t smem_u32(const void* p) {
    uint32_t a;
    asm("{ .reg .u64 t; cvta.to.shared.u64 t, %1; cvt.u32.u64 %0, t; }"
        : "=r"(a) : "l"(p));
    return a;
}
__device__ __forceinline__ uint32_t f2tf32(float f) {
    uint32_t r;
    asm("cvt.rna.tf32.f32 %0, %1;" : "=r"(r) : "f"(f));
    return r;
}
__device__ __forceinline__ float rnaf(float f) {
    return __uint_as_float(f2tf32(f));
}
__device__ __forceinline__ void mma8(float* c, const uint32_t* a,
                                     const uint32_t* b) {
    asm volatile(
        "mma.sync.aligned.m16n8k8.row.col.f32.tf32.tf32.f32 "
        "{%0,%1,%2,%3}, {%4,%5,%6,%7}, {%8,%9}, {%0,%1,%2,%3};"
        : "+f"(c[0]), "+f"(c[1]), "+f"(c[2]), "+f"(c[3])
        : "r"(a[0]), "r"(a[1]), "r"(a[2]), "r"(a[3]), "r"(b[0]), "r"(b[1]));
}
__device__ __forceinline__ void ldm_x4(uint32_t& r0, uint32_t& r1,
                                       uint32_t& r2, uint32_t& r3,
                                       uint32_t addr) {
    asm volatile(
        "ldmatrix.sync.aligned.m8n8.x4.shared.b16 {%0,%1,%2,%3}, [%4];"
        : "=r"(r0), "=r"(r1), "=r"(r2), "=r"(r3) : "r"(addr));
}

// ===========================================================================
// Init: FIRE log tables (padded u-table: index = rel + UPAD, no clamps)
// ===========================================================================
__global__ void init_tables(const float* __restrict__ cp,
                            const float* __restrict__ lm) {
    const int i = blockIdx.x * blockDim.x + threadIdx.x;
    if (i >= TSEQ + UPAD) return;
    const float c = cp[0];
    const int   rel = i - UPAD;
    g_ut2[i] = logf(fabsf(c * (float)(rel < 0 ? 0 : rel)) + 1.0f);
    if (i < TSEQ) {
        const float thr = fabsf(lm[0] * 512.0f);
        g_invP[i] =
            1.0f / (logf(fabsf(c * fmaxf((float)i, thr)) + 1.0f) + 1e-6f);
    }
}

// ===========================================================================
// tf32 mma.sync GEMM (R4 structure; smem holds PRE-CONVERTED tf32 bits).
// 128x128 CTA tile, BK=16, 256 thr / 8 warps (4M x 2N), warp tile 32x64.
// Fragments: scalar LDS (pitch 20 / 136, conflict-free), zero mainloop cvt.
// Staging: LDG -> cvt.rna -> STS, register double-buffered.
// ===========================================================================
template <int MODE>
__global__ __launch_bounds__(256, 2) void mma_gemm(const float* __restrict__ A,
                                                   const float* __restrict__ Bm,
                                                   const float* __restrict__ bias,
                                                   float* __restrict__ out,
                                                   int K, int N) {
    __shared__ float As[2][128][20];   // [m][k] tf32 bits
    __shared__ float Bs[2][16][136];   // [k][n] tf32 bits

    const int tid   = threadIdx.x;
    const int lane  = tid & 31;
    const int wid   = tid >> 5;
    const int warpM = wid & 3;
    const int warpN = wid >> 2;
    const int m0    = blockIdx.y * 128;
    const int n0    = blockIdx.x * 128;

    // A loader: rows tid>>2 and +64, k-vec (tid&3)*4
    const int ar = tid >> 2;
    const int ak = (tid & 3) * 4;
    const float* Ag = A + (size_t)(m0 + ar) * K + ak;
    // B loader: k-row tid>>4, col vecs (tid&15)*4 and +64
    const int br = tid >> 4;
    const int bc = (tid & 15) * 4;
    const float* Bg = Bm + (size_t)br * N + n0 + bc;

    float4 ra0, ra1, rb0, rb1;
    ra0 = *(const float4*)Ag;
    ra1 = *(const float4*)(Ag + (size_t)64 * K);
    rb0 = *(const float4*)Bg;
    rb1 = *(const float4*)(Bg + 64);

#define STAGE(bi)                                                             \
    do {                                                                      \
        *(float4*)&As[bi][ar][ak] =                                           \
            make_float4(rnaf(ra0.x), rnaf(ra0.y), rnaf(ra0.z), rnaf(ra0.w));  \
        *(float4*)&As[bi][ar + 64][ak] =                                      \
            make_float4(rnaf(ra1.x), rnaf(ra1.y), rnaf(ra1.z), rnaf(ra1.w));  \
        *(float4*)&Bs[bi][br][bc] =                                           \
            make_float4(rnaf(rb0.x), rnaf(rb0.y), rnaf(rb0.z), rnaf(rb0.w));  \
        *(float4*)&Bs[bi][br][bc + 64] =                                      \
            make_float4(rnaf(rb1.x), rnaf(rb1.y), rnaf(rb1.z), rnaf(rb1.w));  \
    } while (0)

    STAGE(0);
    __syncthreads();

    float acc[2][8][4];
#pragma unroll
    for (int mf = 0; mf < 2; mf++)
#pragma unroll
        for (int nf = 0; nf < 8; nf++)
#pragma unroll
            for (int i = 0; i < 4; i++) acc[mf][nf][i] = 0.0f;

    const int r  = lane >> 2;
    const int cq = lane & 3;
    const int nk = K >> 4;

#pragma unroll 1
    for (int it = 0; it < nk; it++) {
        const int  buf = it & 1;
        const bool nxt = (it + 1) < nk;
        if (nxt) {
            const float* ap = Ag + (it + 1) * 16;
            ra0 = *(const float4*)ap;
            ra1 = *(const float4*)(ap + (size_t)64 * K);
            const float* bp = Bg + (size_t)(it + 1) * 16 * N;
            rb0 = *(const float4*)bp;
            rb1 = *(const float4*)(bp + 64);
        }

#pragma unroll
        for (int ks = 0; ks < 2; ks++) {
            const int kb = ks * 8;
            uint32_t af[2][4];
#pragma unroll
            for (int mf = 0; mf < 2; mf++) {
                const int mrow = warpM * 32 + mf * 16 + r;
                af[mf][0] = __float_as_uint(As[buf][mrow][kb + cq]);
                af[mf][1] = __float_as_uint(As[buf][mrow + 8][kb + cq]);
                af[mf][2] = __float_as_uint(As[buf][mrow][kb + cq + 4]);
                af[mf][3] = __float_as_uint(As[buf][mrow + 8][kb + cq + 4]);
            }
#pragma unroll
            for (int nf = 0; nf < 8; nf++) {
                const int ncol = warpN * 64 + nf * 8 + r;
                uint32_t bfr[2];
                bfr[0] = __float_as_uint(Bs[buf][kb + cq][ncol]);
                bfr[1] = __float_as_uint(Bs[buf][kb + cq + 4][ncol]);
                mma8(acc[0][nf], af[0], bfr);
                mma8(acc[1][nf], af[1], bfr);
            }
        }

        if (nxt) STAGE(buf ^ 1);
        __syncthreads();
    }
#undef STAGE

#pragma unroll
    for (int mf = 0; mf < 2; mf++) {
#pragma unroll
        for (int nf = 0; nf < 8; nf++) {
            const int n = n0 + warpN * 64 + nf * 8 + 2 * cq;
            const float bx = bias[n], by = bias[n + 1];
#pragma unroll
            for (int half = 0; half < 2; half++) {
                const int m = m0 + warpM * 32 + mf * 16 + r + half * 8;
                float2 v = make_float2(acc[mf][nf][half * 2] + bx,
                                       acc[mf][nf][half * 2 + 1] + by);
                if (MODE == 0) {
                    const int which = n >> 10;
                    const int hh    = (n & 1023) >> 6;
                    const int d     = n & 63;
                    const int bb    = m >> 11;
                    const int t     = m & 2047;
                    *(float2*)&g_qkv[which * (BSZ * NH * TSEQ * HD) +
                                     ((bb * NH + hh) * TSEQ + t) * HD + d] = v;
                } else {
                    *(float2*)&out[(size_t)m * N + n] = v;
                }
            }
        }
    }
}

// ===========================================================================
// FA2-style flash attention, tf32 mma.sync, fused FIRE bias.
// b2[h] dropped (softmax row-shift invariance); padded u-table (no clamps).
// ===========================================================================
__device__ __forceinline__ float fire_mlp(float nd, const float* sw1,
                                          const float* sb1, const float* sw2) {
    float acc = 0.0f;
#pragma unroll
    for (int w = 0; w < MLPW; w++)
        acc = fmaf(fmaxf(fmaf(nd, sw1[w], sb1[w]), 0.0f), sw2[w], acc);
    return acc;
}

__global__ __launch_bounds__(256) void attn_mma(
        const float* __restrict__ w1, const float* __restrict__ b1,
        const float* __restrict__ w2) {
    __shared__ __align__(16) float Ks[2][32][68];
    __shared__ __align__(16) float Vt[2][64][36];
    __shared__ float sw1[MLPW], sb1[MLPW], sw2[MLPW];
    __shared__ float s_alpha;
    __shared__ int   s_lin;

    const int tid  = threadIdx.x;
    const int lane = tid & 31;
    const int warp = tid >> 5;
    const int h    = blockIdx.y;
    const int b    = blockIdx.z;
    const int q0   = (gridDim.x - 1 - blockIdx.x) * 128;
    const int tw   = q0 + warp * 16;
    const int r    = lane >> 2;
    const int cq   = lane & 3;
    const int t0   = tw + r;
    const int t1   = t0 + 8;

    if (tid < MLPW) {
        sw1[tid] = w1[tid];
        sb1[tid] = b1[tid];
        sw2[tid] = w2[tid * NH + h];
    }
    __syncthreads();
    if (tid == 0) {
        bool  lin = true;
        float a   = 0.0f;
#pragma unroll
        for (int w = 0; w < MLPW; w++) {
            lin = lin && (sb1[w] == 0.0f);
            a   = fmaf(fmaxf(sw1[w], 0.0f), sw2[w], a);
        }
        s_alpha = a;
        s_lin   = lin ? 1 : 0;
    }

    const float invP0 = g_invP[t0];
    const float invP1 = g_invP[t1];

    const float* Qg = g_qkv + (size_t)(b * NH + h) * TSEQ * HD;
    const float* Kg = Qg + (size_t)BSZ * NH * TSEQ * HD;
    const float* Vg = Kg + (size_t)BSZ * NH * TSEQ * HD;

    uint32_t qa[8][4];
#pragma unroll
    for (int kf = 0; kf < 8; kf++) {
        qa[kf][0] = f2tf32(Qg[(size_t)t0 * HD + kf * 8 + cq] * 0.125f);
        qa[kf][1] = f2tf32(Qg[(size_t)t1 * HD + kf * 8 + cq] * 0.125f);
        qa[kf][2] = f2tf32(Qg[(size_t)t0 * HD + kf * 8 + cq + 4] * 0.125f);
        qa[kf][3] = f2tf32(Qg[(size_t)t1 * HD + kf * 8 + cq + 4] * 0.125f);
    }

    float o[8][4];
#pragma unroll
    for (int nd = 0; nd < 8; nd++)
#pragma unroll
        for (int i = 0; i < 4; i++) o[nd][i] = 0.0f;
    float m0 = -1e30f, m1 = -1e30f, l0 = 0.0f, l1 = 0.0f;

    const int krow = tid >> 3;
    const int kc   = tid & 7;
    float4 kreg0, kreg1;
    float  vreg[8];

    {
        const float4* kp = (const float4*)&Kg[(size_t)krow * HD];
        kreg0 = kp[kc];
        kreg1 = kp[kc + 8];
#pragma unroll
        for (int i = 0; i < 8; i++)
            vreg[i] = Vg[(size_t)krow * HD + kc + 8 * i];
        float4 c0 = make_float4(rnaf(kreg0.x), rnaf(kreg0.y), rnaf(kreg0.z), rnaf(kreg0.w));
        float4 c1 = make_float4(rnaf(kreg1.x), rnaf(kreg1.y), rnaf(kreg1.z), rnaf(kreg1.w));
        *(float4*)&Ks[0][krow][kc * 4]      = c0;
        *(float4*)&Ks[0][krow][kc * 4 + 32] = c1;
#pragma unroll
        for (int i = 0; i < 8; i++) Vt[0][kc + 8 * i][krow] = rnaf(vreg[i]);
    }
    __syncthreads();

    const int   lin   = s_lin;
    const float alpha = s_alpha;
    const float ai0   = alpha * invP0;
    const float ai1   = alpha * invP1;
    const float* ut   = g_ut2 + UPAD;

    const int nt = (q0 + 128) >> 5;
#pragma unroll 1
    for (int it = 0; it < nt; it++) {
        const int  buf = it & 1;
        const int  s0  = it * 32;
        const bool nxt = (it + 1) < nt;

        if (nxt) {
            const float4* kp = (const float4*)&Kg[(size_t)(s0 + 32 + krow) * HD];
            kreg0 = kp[kc];
            kreg1 = kp[kc + 8];
#pragma unroll
            for (int i = 0; i < 8; i++)
                vreg[i] = Vg[(size_t)(s0 + 32 + krow) * HD + kc + 8 * i];
        }

        if (s0 <= tw + 15) {
            const bool     msk = (s0 + 31) > tw;
            const uint32_t kb  = smem_u32(&Ks[buf][0][0]);
            const uint32_t vb  = smem_u32(&Vt[buf][0][0]);

            float s[4][4];
#pragma unroll
            for (int nf = 0; nf < 4; nf++) {
                s[nf][0] = s[nf][1] = s[nf][2] = s[nf][3] = 0.0f;
#pragma unroll
                for (int kfp = 0; kfp < 4; kfp++) {
                    uint32_t bb[4];
                    const uint32_t addr = kb +
                        4u * ((uint32_t)(8 * nf + (lane & 7)) * 68u +
                              16u * kfp + 4u * (lane >> 3));
                    ldm_x4(bb[0], bb[1], bb[2], bb[3], addr);
                    mma8(s[nf], qa[2 * kfp], bb);
                    mma8(s[nf], qa[2 * kfp + 1], bb + 2);
                }
            }

            float mt0 = -1e30f, mt1 = -1e30f;
#pragma unroll
            for (int nf = 0; nf < 4; nf++) {
                const int k0    = s0 + nf * 8 + 2 * cq;
                const int rel00 = t0 - k0;
                const float u00 = __ldg(&ut[rel00]);
                const float u01 = __ldg(&ut[rel00 - 1]);
                const float u10 = __ldg(&ut[rel00 + 8]);
                const float u11 = __ldg(&ut[rel00 + 7]);
                if (lin) {
                    s[nf][0] = fmaf(ai0, u00, s[nf][0]);
                    s[nf][1] = fmaf(ai0, u01, s[nf][1]);
                    s[nf][2] = fmaf(ai1, u10, s[nf][2]);
                    s[nf][3] = fmaf(ai1, u11, s[nf][3]);
                } else {
                    s[nf][0] += fire_mlp(u00 * invP0, sw1, sb1, sw2);
                    s[nf][1] += fire_mlp(u01 * invP0, sw1, sb1, sw2);
                    s[nf][2] += fire_mlp(u10 * invP1, sw1, sb1, sw2);
                    s[nf][3] += fire_mlp(u11 * invP1, sw1, sb1, sw2);
                }
                if (msk) {
                    if (rel00 < 0)     s[nf][0] = -1e30f;
                    if (rel00 - 1 < 0) s[nf][1] = -1e30f;
                    if (rel00 + 8 < 0) s[nf][2] = -1e30f;
                    if (rel00 + 7 < 0) s[nf][3] = -1e30f;
                }
                mt0 = fmaxf(mt0, fmaxf(s[nf][0], s[nf][1]));
                mt1 = fmaxf(mt1, fmaxf(s[nf][2], s[nf][3]));
            }
            mt0 = fmaxf(mt0, __shfl_xor_sync(0xffffffffu, mt0, 1));
            mt0 = fmaxf(mt0, __shfl_xor_sync(0xffffffffu, mt0, 2));
            mt1 = fmaxf(mt1, __shfl_xor_sync(0xffffffffu, mt1, 1));
            mt1 = fmaxf(mt1, __shfl_xor_sync(0xffffffffu, mt1, 2));

            const float mn0 = fmaxf(m0, mt0);
            const float mn1 = fmaxf(m1, mt1);
            const float f0  = __expf(m0 - mn0);
            const float f1  = __expf(m1 - mn1);
            m0 = mn0; m1 = mn1;
            l0 *= f0;  l1 *= f1;
#pragma unroll
            for (int nd = 0; nd < 8; nd++) {
                o[nd][0] *= f0; o[nd][1] *= f0;
                o[nd][2] *= f1; o[nd][3] *= f1;
            }
#pragma unroll
            for (int nf = 0; nf < 4; nf++) {
                s[nf][0] = __expf(s[nf][0] - m0);
                s[nf][1] = __expf(s[nf][1] - m0);
                s[nf][2] = __expf(s[nf][2] - m1);
                s[nf][3] = __expf(s[nf][3] - m1);
                l0 += s[nf][0] + s[nf][1];
                l1 += s[nf][2] + s[nf][3];
            }

            const int src1 = (lane & 28) | (cq >> 1);
            const int src2 = src1 + 2;
#pragma unroll
            for (int kf2 = 0; kf2 < 4; kf2++) {
                const float x0 = __shfl_sync(0xffffffffu, s[kf2][0], src1);
                const float x1 = __shfl_sync(0xffffffffu, s[kf2][1], src1);
                const float y0 = __shfl_sync(0xffffffffu, s[kf2][0], src2);
                const float y1 = __shfl_sync(0xffffffffu, s[kf2][1], src2);
                const float x2 = __shfl_sync(0xffffffffu, s[kf2][2], src1);
                const float x3 = __shfl_sync(0xffffffffu, s[kf2][3], src1);
                const float y2 = __shfl_sync(0xffffffffu, s[kf2][2], src2);
                const float y3 = __shfl_sync(0xffffffffu, s[kf2][3], src2);
                uint32_t pa[4];
                pa[0] = f2tf32((cq & 1) ? x1 : x0);
                pa[1] = f2tf32((cq & 1) ? x3 : x2);
                pa[2] = f2tf32((cq & 1) ? y1 : y0);
                pa[3] = f2tf32((cq & 1) ? y3 : y2);
#pragma unroll
                for (int g = 0; g < 4; g++) {
                    uint32_t bv[4];
                    const uint32_t addr = vb +
                        4u * ((uint32_t)(8 * (2 * g + (lane >> 4)) + (lane & 7)) * 36u +
                              8u * kf2 + 4u * ((lane >> 3) & 1));
                    ldm_x4(bv[0], bv[1], bv[2], bv[3], addr);
                    mma8(o[2 * g], pa, bv);
                    mma8(o[2 * g + 1], pa, bv + 2);
                }
            }
        }

        if (nxt) {
            const int nb = buf ^ 1;
            float4 c0 = make_float4(rnaf(kreg0.x), rnaf(kreg0.y), rnaf(kreg0.z), rnaf(kreg0.w));
            float4 c1 = make_float4(rnaf(kreg1.x), rnaf(kreg1.y), rnaf(kreg1.z), rnaf(kreg1.w));
            *(float4*)&Ks[nb][krow][kc * 4]      = c0;
            *(float4*)&Ks[nb][krow][kc * 4 + 32] = c1;
#pragma unroll
            for (int i = 0; i < 8; i++) Vt[nb][kc + 8 * i][krow] = rnaf(vreg[i]);
        }
        __syncthreads();
    }

    l0 += __shfl_xor_sync(0xffffffffu, l0, 1);
    l0 += __shfl_xor_sync(0xffffffffu, l0, 2);
    l1 += __shfl_xor_sync(0xffffffffu, l1, 1);
    l1 += __shfl_xor_sync(0xffffffffu, l1, 2);
    const float inv0 = 1.0f / l0;
    const float inv1 = 1.0f / l1;
    float* y0p = &g_y[((size_t)(b * TSEQ) + t0) * CDIM + h * HD];
    float* y1p = &g_y[((size_t)(b * TSEQ) + t1) * CDIM + h * HD];
#pragma unroll
    for (int nd = 0; nd < 8; nd++) {
        const int d = nd * 8 + 2 * cq;
        *(float2*)&y0p[d] = make_float2(o[nd][0] * inv0, o[nd][1] * inv0);
        *(float2*)&y1p[d] = make_float2(o[nd][2] * inv1, o[nd][3] * inv1);
    }
}

// ===========================================================================
// Launch
// ===========================================================================
extern "C" void kernel_launch(void* const* d_in, const int* in_sizes, int n_in,
                              void* d_out, int out_size) {
    const float* x     = (const float*)d_in[0];
    const float* Wqkv  = (const float*)d_in[1];
    const float* bqkv  = (const float*)d_in[2];
    const float* Wproj = (const float*)d_in[3];
    const float* bproj = (const float*)d_in[4];
    const float* w1    = (const float*)d_in[5];
    const float* b1    = (const float*)d_in[6];
    const float* w2    = (const float*)d_in[7];
    const float* cpar  = (const float*)d_in[9];
    const float* lmul  = (const float*)d_in[10];
    float* out = (float*)d_out;

    init_tables<<<(TSEQ + UPAD + 255) / 256, 256>>>(cpar, lmul);

    mma_gemm<0><<<dim3(3 * CDIM / 128, BSZ * TSEQ / 128), 256>>>(
        x, Wqkv, bqkv, nullptr, CDIM, 3 * CDIM);

    attn_mma<<<dim3(TSEQ / 128, NH, BSZ), 256>>>(w1, b1, w2);

    float* gy_ptr = nullptr;
    cudaGetSymbolAddress((void**)&gy_ptr, g_y);
    mma_gemm<1><<<dim3(CDIM / 128, BSZ * TSEQ / 128), 256>>>(
        gy_ptr, Wproj, bproj, out, CDIM, CDIM);
}